// round 11
// baseline (speedup 1.0000x reference)
#include <cuda_runtime.h>

// SiluAndMul: x [M, 2N] fp32 -> out [M, N] fp32, out = silu(x[:, :N]) * x[:, N:]
// M = 16384, N = 11008. Pure HBM-bound: 2.164 GB/launch.
//
// R11: block=64 endpoint of the CTA-granularity sweep.
//   block=256: occ 79.6%, DRAM 90.0%, 7133 GB/s (profiled 299.2us)
//   block=128: occ 84.6%, DRAM 91.2%, 7233 GB/s (profiled 295.0us)  <- trend
//   block=64:  2-warp CTAs -> 32 CTAs/SM = 64 warps = full occupancy.
// Bonus: N4 = 2752 = 64*43 exactly -> zero tail, no bounds predicate,
// grid (43, 16384) = 704,512 full CTAs (CTA count is free; it IS the MLP).
// Plain evict-normal ld/st (streaming hints measured slower, R2-R4).

static constexpr int M = 16384;
static constexpr int N = 11008;         // output cols
static constexpr int TWO_N = 2 * N;     // input row stride (floats)
static constexpr int N4 = N / 4;        // 2752 float4 per output row
static constexpr int BLOCK = 64;
static constexpr int GRID_X = N4 / BLOCK;   // 43, exact

__global__ __launch_bounds__(BLOCK) void silu_and_mul_kernel(
    const float* __restrict__ x, float* __restrict__ out)
{
    const int col4 = blockIdx.x * BLOCK + threadIdx.x;  // always < N4 (exact cover)
    const long long row = blockIdx.y;

    const float4* gate4 = reinterpret_cast<const float4*>(x + row * TWO_N);
    const float4* up4   = reinterpret_cast<const float4*>(x + row * TWO_N + N);
    float4* out4        = reinterpret_cast<float4*>(out + row * (long long)N);

    float4 g = gate4[col4];
    float4 u = up4[col4];

    float4 r;
    r.x = (g.x * __frcp_rn(1.0f + __expf(-g.x))) * u.x;
    r.y = (g.y * __frcp_rn(1.0f + __expf(-g.y))) * u.y;
    r.z = (g.z * __frcp_rn(1.0f + __expf(-g.z))) * u.z;
    r.w = (g.w * __frcp_rn(1.0f + __expf(-g.w))) * u.w;

    out4[col4] = r;
}

extern "C" void kernel_launch(void* const* d_in, const int* in_sizes, int n_in,
                              void* d_out, int out_size)
{
    const float* x = (const float*)d_in[0];
    float* out = (float*)d_out;

    dim3 block(BLOCK);
    dim3 grid(GRID_X, M);   // (43, 16384)
    silu_and_mul_kernel<<<grid, block>>>(x, out);
}

// round 12
// speedup vs baseline: 1.2035x; 1.2035x over previous
#include <cuda_runtime.h>

// SiluAndMul: x [M, 2N] fp32 -> out [M, N] fp32, out = silu(x[:, :N]) * x[:, N:]
// M = 16384, N = 11008. Pure HBM-bound: 2.164 GB/launch.
//
// FINAL kernel — 11-round sweep on GB300 (sm_103a). Block-size occupancy curve
// is non-monotone (CTA-refill-rate limits small blocks, warp-slot granularity
// limits large ones):
//   block=64:  occ 42.2%, DRAM 74.6%, 361us  (CTA delivery starves SMs)
//   block=128: occ 84.6%, DRAM 91.2%, 295us  <- session-best profiled, 7233 GB/s
//   block=256: occ 79.6%, DRAM 90.0%, 299us
// Other closed axes: streaming cache hints hurt (~2us each, R2-R4); deeper
// per-thread unroll neutral (R3); persistent grid catastrophic (MLP collapse,
// R8); 64-bit flat indexing neutral-worse (R6).
// Governing mechanism: bandwidth = independent in-flight loads; the huge
// one-shot CTA count is the parallelism that saturates the DRAM queues.
// 90.4% of 8 TB/s spec achieved; remainder is refresh + R/W turnaround.

static constexpr int M = 16384;
static constexpr int N = 11008;         // output cols
static constexpr int TWO_N = 2 * N;     // input row stride (floats)
static constexpr int N4 = N / 4;        // 2752 float4 per output row
static constexpr int BLOCK = 128;

__global__ __launch_bounds__(BLOCK) void silu_and_mul_kernel(
    const float* __restrict__ x, float* __restrict__ out)
{
    const int col4 = blockIdx.x * BLOCK + threadIdx.x;  // float4 column index
    if (col4 >= N4) return;
    const long long row = blockIdx.y;

    const float4* gate4 = reinterpret_cast<const float4*>(x + row * TWO_N);
    const float4* up4   = reinterpret_cast<const float4*>(x + row * TWO_N + N);
    float4* out4        = reinterpret_cast<float4*>(out + row * (long long)N);

    float4 g = gate4[col4];
    float4 u = up4[col4];

    float4 r;
    r.x = (g.x * __frcp_rn(1.0f + __expf(-g.x))) * u.x;
    r.y = (g.y * __frcp_rn(1.0f + __expf(-g.y))) * u.y;
    r.z = (g.z * __frcp_rn(1.0f + __expf(-g.z))) * u.z;
    r.w = (g.w * __frcp_rn(1.0f + __expf(-g.w))) * u.w;

    out4[col4] = r;
}

extern "C" void kernel_launch(void* const* d_in, const int* in_sizes, int n_in,
                              void* d_out, int out_size)
{
    const float* x = (const float*)d_in[0];
    float* out = (float*)d_out;

    dim3 block(BLOCK);
    dim3 grid((N4 + BLOCK - 1) / BLOCK, M);   // (22, 16384)
    silu_and_mul_kernel<<<grid, block>>>(x, out);
}

// round 13
// speedup vs baseline: 1.2081x; 1.0038x over previous
#include <cuda_runtime.h>

// SiluAndMul: x [M, 2N] fp32 -> out [M, N] fp32, out = silu(x[:, :N]) * x[:, N:]
// M = 16384, N = 11008. Pure HBM-bound: 2.164 GB/launch.
//
// R13 probe: block=192, interpolating the non-monotone block-size curve:
//   block=64:  occ 42.2%, DRAM 74.6%  (CTA refill starves SMs)
//   block=128: occ 85.4%, DRAM 91.4%, 7245 GB/s, timed 299.2us  <- best so far
//   block=256: occ 79.6%, DRAM 90.0%
// block=192: 6-warp CTAs — 1.5x longer CTA lifetime than 128 (less refill
// pressure) with finer warp-slot packing than 256. If refill is the residual
// limiter at 128, occ -> ~88-90% and DRAM -> ~92%.
// All other axes closed: plain evict-normal ld/st, 1 float4/thread, 2D grid.

static constexpr int M = 16384;
static constexpr int N = 11008;         // output cols
static constexpr int TWO_N = 2 * N;     // input row stride (floats)
static constexpr int N4 = N / 4;        // 2752 float4 per output row
static constexpr int BLOCK = 192;

__global__ __launch_bounds__(BLOCK) void silu_and_mul_kernel(
    const float* __restrict__ x, float* __restrict__ out)
{
    const int col4 = blockIdx.x * BLOCK + threadIdx.x;  // float4 column index
    if (col4 >= N4) return;
    const long long row = blockIdx.y;

    const float4* gate4 = reinterpret_cast<const float4*>(x + row * TWO_N);
    const float4* up4   = reinterpret_cast<const float4*>(x + row * TWO_N + N);
    float4* out4        = reinterpret_cast<float4*>(out + row * (long long)N);

    float4 g = gate4[col4];
    float4 u = up4[col4];

    float4 r;
    r.x = (g.x * __frcp_rn(1.0f + __expf(-g.x))) * u.x;
    r.y = (g.y * __frcp_rn(1.0f + __expf(-g.y))) * u.y;
    r.z = (g.z * __frcp_rn(1.0f + __expf(-g.z))) * u.z;
    r.w = (g.w * __frcp_rn(1.0f + __expf(-g.w))) * u.w;

    out4[col4] = r;
}

extern "C" void kernel_launch(void* const* d_in, const int* in_sizes, int n_in,
                              void* d_out, int out_size)
{
    const float* x = (const float*)d_in[0];
    float* out = (float*)d_out;

    dim3 block(BLOCK);
    dim3 grid((N4 + BLOCK - 1) / BLOCK, M);   // (15, 16384)
    silu_and_mul_kernel<<<grid, block>>>(x, out);
}